// round 13
// baseline (speedup 1.0000x reference)
#include <cuda_runtime.h>
#include <cuda_fp16.h>
#include <cstddef>

#define MAX_N (512 * 512)
#define NB 8

// Cell table: for each grid cell c = jj*nx+ii, 4 x uint4 (one per batch-pair p).
// Each uint4 = 4 half2: (v00,v10,v01,v11), each half2 = (batch 2p, batch 2p+1).
// 64B per cell.
__device__ uint4 g_cell[(size_t)MAX_N * 4];

// Uniform constants from prep:
// [0]=ox(=-x0*inv_dx) [1]=oy [2]=inv_dx [3]=inv_dy [4]=nxm2 [5]=nym2 [6]=nx(bits) [7]=nxf
__device__ __align__(16) float g_consts[8];

static __device__ __forceinline__ unsigned h2u(__half2 h) {
    return *reinterpret_cast<unsigned*>(&h);
}
static __device__ __forceinline__ __half2 u2h(unsigned u) {
    return *reinterpret_cast<__half2*>(&u);
}

// ---------------------------------------------------------------------------
// Consts kernel: single thread, writes the uniform constants.
// ---------------------------------------------------------------------------
__global__ void prep_consts(
    const float* __restrict__ src_x,
    const float* __restrict__ src_y,
    const int* __restrict__ p_nx,
    const int* __restrict__ p_ny)
{
    const int nx = p_nx[0];
    const int ny = p_ny[0];
    const float x0 = src_x[0];
    const float x1 = src_x[nx - 1];
    const float y0 = src_y[0];
    const float y1 = src_y[(size_t)(ny - 1) * nx];
    const float inv_dx = (float)(nx - 1) / (x1 - x0);
    const float inv_dy = (float)(ny - 1) / (y1 - y0);
    g_consts[0] = -x0 * inv_dx;
    g_consts[1] = -y0 * inv_dy;
    g_consts[2] = inv_dx;
    g_consts[3] = inv_dy;
    g_consts[4] = (float)(nx - 2);
    g_consts[5] = (float)(ny - 2);
    g_consts[6] = __int_as_float(nx);
    g_consts[7] = (float)nx;
}

// ---------------------------------------------------------------------------
// Prep v5: 2D grid — blockIdx.y = row jj (0..ny-2), no division, no
// row-crossing logic. Thread = (quad within row, batch-pair p); same proven
// v3 load/store pattern (float4 row loads, coalesced 16B-per-tid stores).
// Requires nx % 4 == 0 (checked on host via N; fallback kernel otherwise).
// ---------------------------------------------------------------------------
__global__ void __launch_bounds__(256) prep_cell_v5(
    const float* __restrict__ x,
    int nx_cells_round,   // unused placeholder for signature stability
    int N)
{
    const int nx = __float_as_int(g_consts[6]);
    const int jj = blockIdx.y;
    const int qcol = blockIdx.x * 64 + (threadIdx.x >> 2);  // quad column
    const int p    = threadIdx.x & 3;
    const int ii0  = qcol * 4;
    if (ii0 >= nx) return;

    const int c0 = jj * nx + ii0;

    const float* __restrict__ xb0 = x + (size_t)(2 * p) * N;
    const float* __restrict__ xb1 = xb0 + N;

    float r0[5], r1[5], s0[5], s1[5];
    float4 v;
    v = *reinterpret_cast<const float4*>(xb0 + c0);
    r0[0] = v.x; r0[1] = v.y; r0[2] = v.z; r0[3] = v.w;
    r0[4] = __ldg(xb0 + min(c0 + 4, N - 1));
    v = *reinterpret_cast<const float4*>(xb0 + c0 + nx);
    r1[0] = v.x; r1[1] = v.y; r1[2] = v.z; r1[3] = v.w;
    r1[4] = __ldg(xb0 + min(c0 + nx + 4, N - 1));
    v = *reinterpret_cast<const float4*>(xb1 + c0);
    s0[0] = v.x; s0[1] = v.y; s0[2] = v.z; s0[3] = v.w;
    s0[4] = __ldg(xb1 + min(c0 + 4, N - 1));
    v = *reinterpret_cast<const float4*>(xb1 + c0 + nx);
    s1[0] = v.x; s1[1] = v.y; s1[2] = v.z; s1[3] = v.w;
    s1[4] = __ldg(xb1 + min(c0 + nx + 4, N - 1));

    // Convert each point once (compiler CSEs shared neighbors).
    unsigned h0[5], h1[5];
#pragma unroll
    for (int i = 0; i < 5; i++) {
        h0[i] = h2u(__floats2half2_rn(r0[i], s0[i]));
        h1[i] = h2u(__floats2half2_rn(r1[i], s1[i]));
    }

    uint4* __restrict__ dst = &g_cell[(size_t)c0 * 4 + p];
    const int imax = min(4, nx - 1 - ii0);   // cells with ii <= nx-2
#pragma unroll
    for (int i = 0; i < 4; i++) {
        if (i < imax) {
            uint4 w;
            w.x = h0[i];
            w.y = h0[i + 1];
            w.z = h1[i];
            w.w = h1[i + 1];
            dst[(size_t)i * 4] = w;
        }
    }
}

// ---------------------------------------------------------------------------
// Prep fallback (nx % 4 != 0): v3-style scalar per (cell, pair).
// ---------------------------------------------------------------------------
__global__ void __launch_bounds__(256) prep_cell_scalar(
    const float* __restrict__ x,
    const int* __restrict__ p_nx,
    const int* __restrict__ p_ny,
    int N)
{
    const int idx = blockIdx.x * blockDim.x + threadIdx.x;
    const int c = idx >> 2;
    const int p = idx & 3;
    if (c >= N) return;
    const int nx = p_nx[0];
    const int ny = p_ny[0];
    const int jj = c / nx;
    const int ii = c - jj * nx;
    if (ii > nx - 2 || jj > ny - 2) return;

    const float* __restrict__ xb0 = x + (size_t)(2 * p) * N;
    const float* __restrict__ xb1 = xb0 + N;
    uint4 w;
    w.x = h2u(__floats2half2_rn(__ldg(xb0 + c),          __ldg(xb1 + c)));
    w.y = h2u(__floats2half2_rn(__ldg(xb0 + c + 1),      __ldg(xb1 + c + 1)));
    w.z = h2u(__floats2half2_rn(__ldg(xb0 + c + nx),     __ldg(xb1 + c + nx)));
    w.w = h2u(__floats2half2_rn(__ldg(xb0 + c + nx + 1), __ldg(xb1 + c + nx + 1)));
    g_cell[(size_t)c * 4 + p] = w;
}

// ---------------------------------------------------------------------------
// Interp v5: v4 minus the index clamps. Dataset guarantee (targets in
// [eps, 1-eps]) implies floor(fx) in [0, nx-2] already, so the 4 FMNMX per
// target are no-ops; the generic fallback keeps full clamping.
// Index math: 2 FMA, 2 FRND, 2 FADD, 1 FMA, 1 F2I, 1 SHF = 7 instr/target.
// ---------------------------------------------------------------------------
__global__ void __launch_bounds__(256, 8) interp_fp16_v5(
    const float* __restrict__ tgt_x,
    const float* __restrict__ tgt_y,
    float* __restrict__ out,
    int T)
{
    const int lane = threadIdx.x & 31;
    const int warp = (blockIdx.x * blockDim.x + threadIdx.x) >> 5;
    const int g    = lane >> 2;
    const int p    = lane & 3;
    const int tg   = warp * 32 + g * 4;
    if (tg >= T) return;

    const float4 k0 = *reinterpret_cast<const float4*>(&g_consts[0]);
    const float4 k1 = *reinterpret_cast<const float4*>(&g_consts[4]);
    const float ox = k0.x, oy = k0.y, inv_dx = k0.z, inv_dy = k0.w;
    const float nxf = k1.w;

    const char* __restrict__ cellp = reinterpret_cast<const char*>(g_cell) + (p << 4);

    const bool full = (tg + 3 < T);

    float tx[4], ty[4];
    if (full) {
        const float4 tx4 = *reinterpret_cast<const float4*>(tgt_x + tg);
        const float4 ty4 = *reinterpret_cast<const float4*>(tgt_y + tg);
        tx[0] = tx4.x; tx[1] = tx4.y; tx[2] = tx4.z; tx[3] = tx4.w;
        ty[0] = ty4.x; ty[1] = ty4.y; ty[2] = ty4.z; ty[3] = ty4.w;
    } else {
#pragma unroll
        for (int j = 0; j < 4; j++) {
            const int t = min(tg + j, T - 1);
            tx[j] = tgt_x[t];
            ty[j] = tgt_y[t];
        }
    }

    float o0[4], o1[4];
#pragma unroll
    for (int j = 0; j < 4; j++) {
        const float fx = fmaf(tx[j], inv_dx, ox);
        const float fy = fmaf(ty[j], inv_dy, oy);
        const float ixf = floorf(fx);            // in [0, nx-2] by data bounds
        const float iyf = floorf(fy);            // in [0, ny-2]
        const float u = fx - ixf;
        const float v = fy - iyf;
        const float basef = fmaf(iyf, nxf, ixf); // exact: < 2^24
        const unsigned off = (unsigned)__float2int_rn(basef) << 6;

        const uint4 cv = __ldg(reinterpret_cast<const uint4*>(cellp + off));

        const float s  = u + v;
        const float m  = 1.0f - s;
        const float mn = fminf(m, 0.0f);
        const float wA  = fabsf(m);
        const float w10 = u + mn;          // lower: u      upper: 1-v
        const float w01 = v + mn;          // lower: v      upper: 1-u
        const unsigned ua = (m >= 0.0f) ? cv.x : cv.w;

        const float2 fA  = __half22float2(u2h(ua));
        const float2 f10 = __half22float2(u2h(cv.y));
        const float2 f01 = __half22float2(u2h(cv.z));

        o0[j] = fmaf(wA, fA.x, fmaf(w10, f10.x, w01 * f01.x));
        o1[j] = fmaf(wA, fA.y, fmaf(w10, f10.y, w01 * f01.y));
    }

    const int b0 = 2 * p;
    if (full) {
        *reinterpret_cast<float4*>(out + (size_t)b0 * T + tg) =
            make_float4(o0[0], o0[1], o0[2], o0[3]);
        *reinterpret_cast<float4*>(out + (size_t)(b0 + 1) * T + tg) =
            make_float4(o1[0], o1[1], o1[2], o1[3]);
    } else {
#pragma unroll
        for (int j = 0; j < 4; j++) {
            if (tg + j < T) {
                out[(size_t)b0 * T + tg + j] = o0[j];
                out[(size_t)(b0 + 1) * T + tg + j] = o1[j];
            }
        }
    }
}

// ---------------------------------------------------------------------------
// Generic fallback (any B), fp32 exact, full clamping.
// ---------------------------------------------------------------------------
__global__ void interp_generic_kernel(
    const float* __restrict__ x,
    const float* __restrict__ src_x,
    const float* __restrict__ src_y,
    const float* __restrict__ tgt_x,
    const float* __restrict__ tgt_y,
    const int* __restrict__ p_nx,
    const int* __restrict__ p_ny,
    float* __restrict__ out,
    int T, int B, int N)
{
    int t = blockIdx.x * blockDim.x + threadIdx.x;
    if (t >= T) return;

    const int nx = p_nx[0];
    const int ny = p_ny[0];
    const float x0 = src_x[0];
    const float x1 = src_x[nx - 1];
    const float y0 = src_y[0];
    const float y1 = src_y[(size_t)(ny - 1) * nx];
    const float inv_dx = (float)(nx - 1) / (x1 - x0);
    const float inv_dy = (float)(ny - 1) / (y1 - y0);

    const float fx = (tgt_x[t] - x0) * inv_dx;
    const float fy = (tgt_y[t] - y0) * inv_dy;

    float ixf = fminf(fmaxf(floorf(fx), 0.0f), (float)(nx - 2));
    float iyf = fminf(fmaxf(floorf(fy), 0.0f), (float)(ny - 2));
    const float u = fx - ixf;
    const float v = fy - iyf;
    const int base = (int)iyf * nx + (int)ixf;

    const bool lower = (u + v <= 1.0f);
    const int iA = lower ? base : (base + nx + 1);
    const int iB = base + 1;
    const int iC = base + nx;
    const float wA = lower ? (1.0f - u - v) : (u + v - 1.0f);
    const float wB = lower ? u : (1.0f - v);
    const float wC = lower ? v : (1.0f - u);

    for (int b = 0; b < B; b++) {
        const float* xb = x + (size_t)b * N;
        out[(size_t)b * T + t] = wA * xb[iA] + wB * xb[iB] + wC * xb[iC];
    }
}

extern "C" void kernel_launch(void* const* d_in, const int* in_sizes, int n_in,
                              void* d_out, int out_size)
{
    const float* x     = (const float*)d_in[0];
    const float* src_x = (const float*)d_in[1];
    const float* src_y = (const float*)d_in[2];
    const float* tgt_x = (const float*)d_in[3];
    const float* tgt_y = (const float*)d_in[4];
    const int*   p_nx  = (const int*)d_in[5];
    const int*   p_ny  = (const int*)d_in[6];
    float* out = (float*)d_out;

    const int N = in_sizes[1];          // nx*ny grid points
    const int T = in_sizes[3];          // target count
    const int B = in_sizes[0] / N;      // batches

    if (B == NB && N <= MAX_N) {
        prep_consts<<<1, 1>>>(src_x, src_y, p_nx, p_ny);

        // Host-side shape inference: the reference grid is square (nx == ny),
        // N = nx*ny. Recover nx to build the 2D prep grid; verify square.
        int nxh = 1;
        while (nxh * nxh < N) nxh++;
        if (nxh * nxh == N && (nxh & 3) == 0) {
            dim3 grid((nxh + 255) / 256, nxh - 1);   // x: 64 quads/block, y: rows
            prep_cell_v5<<<grid, 256>>>(x, 0, N);
        } else {
            const int prep_threads = 4 * N;
            prep_cell_scalar<<<(prep_threads + 255) / 256, 256>>>(x, p_nx, p_ny, N);
        }

        const int blocks = (T + 255) / 256;
        interp_fp16_v5<<<blocks, 256>>>(tgt_x, tgt_y, out, T);
    } else {
        const int threads = 256;
        interp_generic_kernel<<<(T + threads - 1) / threads, threads>>>(
            x, src_x, src_y, tgt_x, tgt_y, p_nx, p_ny, out, T, B, N);
    }
}

// round 14
// speedup vs baseline: 1.0592x; 1.0592x over previous
#include <cuda_runtime.h>
#include <cuda_fp16.h>
#include <cstddef>

#define MAX_N (512 * 512)
#define NB 8

// Cell table: for each grid cell c = jj*nx+ii, 4 x uint4 (one per batch-pair p).
// Each uint4 = 4 half2: (v00,v10,v01,v11), each half2 = (batch 2p, batch 2p+1).
// 64B per cell.
__device__ uint4 g_cell[(size_t)MAX_N * 4];

// Uniform constants for interp:
// [0]=ox(=-x0*inv_dx) [1]=oy [2]=inv_dx [3]=inv_dy [4]=nxm2 [5]=nym2 [6]=nx(bits) [7]=nxf
__device__ __align__(16) float g_consts[8];

static __device__ __forceinline__ unsigned h2u(__half2 h) {
    return *reinterpret_cast<unsigned*>(&h);
}
static __device__ __forceinline__ __half2 u2h(unsigned u) {
    return *reinterpret_cast<__half2*>(&u);
}

// ---------------------------------------------------------------------------
// Prep v6: 2D grid, nx passed from host (square-grid inference). Thread
// (0,0) of block (0,0) also computes the interp constants inline — no
// separate serial consts kernel (R13's 5us regression).
// blockIdx.y = row jj (0..ny-2); thread = (quad column, batch-pair p).
// ---------------------------------------------------------------------------
__global__ void __launch_bounds__(256) prep_cell_v6(
    const float* __restrict__ x,
    const float* __restrict__ src_x,
    const float* __restrict__ src_y,
    int nx, int ny, int N)
{
    if (blockIdx.x == 0 && blockIdx.y == 0 && threadIdx.x == 0) {
        const float x0 = src_x[0];
        const float x1 = src_x[nx - 1];
        const float y0 = src_y[0];
        const float y1 = src_y[(size_t)(ny - 1) * nx];
        const float inv_dx = (float)(nx - 1) / (x1 - x0);
        const float inv_dy = (float)(ny - 1) / (y1 - y0);
        g_consts[0] = -x0 * inv_dx;
        g_consts[1] = -y0 * inv_dy;
        g_consts[2] = inv_dx;
        g_consts[3] = inv_dy;
        g_consts[4] = (float)(nx - 2);
        g_consts[5] = (float)(ny - 2);
        g_consts[6] = __int_as_float(nx);
        g_consts[7] = (float)nx;
    }

    const int jj   = blockIdx.y;
    const int qcol = blockIdx.x * 64 + (threadIdx.x >> 2);  // quad column
    const int p    = threadIdx.x & 3;
    const int ii0  = qcol * 4;
    if (ii0 >= nx) return;

    const int c0 = jj * nx + ii0;

    const float* __restrict__ xb0 = x + (size_t)(2 * p) * N;
    const float* __restrict__ xb1 = xb0 + N;

    float r0[5], r1[5], s0[5], s1[5];
    float4 v;
    v = *reinterpret_cast<const float4*>(xb0 + c0);
    r0[0] = v.x; r0[1] = v.y; r0[2] = v.z; r0[3] = v.w;
    r0[4] = __ldg(xb0 + min(c0 + 4, N - 1));
    v = *reinterpret_cast<const float4*>(xb0 + c0 + nx);
    r1[0] = v.x; r1[1] = v.y; r1[2] = v.z; r1[3] = v.w;
    r1[4] = __ldg(xb0 + min(c0 + nx + 4, N - 1));
    v = *reinterpret_cast<const float4*>(xb1 + c0);
    s0[0] = v.x; s0[1] = v.y; s0[2] = v.z; s0[3] = v.w;
    s0[4] = __ldg(xb1 + min(c0 + 4, N - 1));
    v = *reinterpret_cast<const float4*>(xb1 + c0 + nx);
    s1[0] = v.x; s1[1] = v.y; s1[2] = v.z; s1[3] = v.w;
    s1[4] = __ldg(xb1 + min(c0 + nx + 4, N - 1));

    unsigned h0[5], h1[5];
#pragma unroll
    for (int i = 0; i < 5; i++) {
        h0[i] = h2u(__floats2half2_rn(r0[i], s0[i]));
        h1[i] = h2u(__floats2half2_rn(r1[i], s1[i]));
    }

    uint4* __restrict__ dst = &g_cell[(size_t)c0 * 4 + p];
    const int imax = min(4, nx - 1 - ii0);   // cells with ii <= nx-2
#pragma unroll
    for (int i = 0; i < 4; i++) {
        if (i < imax) {
            uint4 w;
            w.x = h0[i];
            w.y = h0[i + 1];
            w.z = h1[i];
            w.w = h1[i + 1];
            dst[(size_t)i * 4] = w;
        }
    }
}

// ---------------------------------------------------------------------------
// Fallback consts kernel + scalar prep (only when shape inference fails).
// ---------------------------------------------------------------------------
__global__ void prep_consts(
    const float* __restrict__ src_x,
    const float* __restrict__ src_y,
    const int* __restrict__ p_nx,
    const int* __restrict__ p_ny)
{
    const int nx = p_nx[0];
    const int ny = p_ny[0];
    const float x0 = src_x[0];
    const float x1 = src_x[nx - 1];
    const float y0 = src_y[0];
    const float y1 = src_y[(size_t)(ny - 1) * nx];
    const float inv_dx = (float)(nx - 1) / (x1 - x0);
    const float inv_dy = (float)(ny - 1) / (y1 - y0);
    g_consts[0] = -x0 * inv_dx;
    g_consts[1] = -y0 * inv_dy;
    g_consts[2] = inv_dx;
    g_consts[3] = inv_dy;
    g_consts[4] = (float)(nx - 2);
    g_consts[5] = (float)(ny - 2);
    g_consts[6] = __int_as_float(nx);
    g_consts[7] = (float)nx;
}

__global__ void __launch_bounds__(256) prep_cell_scalar(
    const float* __restrict__ x,
    const int* __restrict__ p_nx,
    const int* __restrict__ p_ny,
    int N)
{
    const int idx = blockIdx.x * blockDim.x + threadIdx.x;
    const int c = idx >> 2;
    const int p = idx & 3;
    if (c >= N) return;
    const int nx = p_nx[0];
    const int ny = p_ny[0];
    const int jj = c / nx;
    const int ii = c - jj * nx;
    if (ii > nx - 2 || jj > ny - 2) return;

    const float* __restrict__ xb0 = x + (size_t)(2 * p) * N;
    const float* __restrict__ xb1 = xb0 + N;
    uint4 w;
    w.x = h2u(__floats2half2_rn(__ldg(xb0 + c),          __ldg(xb1 + c)));
    w.y = h2u(__floats2half2_rn(__ldg(xb0 + c + 1),      __ldg(xb1 + c + 1)));
    w.z = h2u(__floats2half2_rn(__ldg(xb0 + c + nx),     __ldg(xb1 + c + nx)));
    w.w = h2u(__floats2half2_rn(__ldg(xb0 + c + nx + 1), __ldg(xb1 + c + nx + 1)));
    g_cell[(size_t)c * 4 + p] = w;
}

// ---------------------------------------------------------------------------
// Interp v5 (unchanged from R12): no index clamps (targets in [eps,1-eps]
// guarantee floor(fx) in [0,nx-2]); branch-free weights; one LDG.128 per
// target per lane quad; regs capped via __launch_bounds__(256, 8).
// ---------------------------------------------------------------------------
__global__ void __launch_bounds__(256, 8) interp_fp16_v5(
    const float* __restrict__ tgt_x,
    const float* __restrict__ tgt_y,
    float* __restrict__ out,
    int T)
{
    const int lane = threadIdx.x & 31;
    const int warp = (blockIdx.x * blockDim.x + threadIdx.x) >> 5;
    const int g    = lane >> 2;
    const int p    = lane & 3;
    const int tg   = warp * 32 + g * 4;
    if (tg >= T) return;

    const float4 k0 = *reinterpret_cast<const float4*>(&g_consts[0]);
    const float4 k1 = *reinterpret_cast<const float4*>(&g_consts[4]);
    const float ox = k0.x, oy = k0.y, inv_dx = k0.z, inv_dy = k0.w;
    const float nxf = k1.w;

    const char* __restrict__ cellp = reinterpret_cast<const char*>(g_cell) + (p << 4);

    const bool full = (tg + 3 < T);

    float tx[4], ty[4];
    if (full) {
        const float4 tx4 = *reinterpret_cast<const float4*>(tgt_x + tg);
        const float4 ty4 = *reinterpret_cast<const float4*>(tgt_y + tg);
        tx[0] = tx4.x; tx[1] = tx4.y; tx[2] = tx4.z; tx[3] = tx4.w;
        ty[0] = ty4.x; ty[1] = ty4.y; ty[2] = ty4.z; ty[3] = ty4.w;
    } else {
#pragma unroll
        for (int j = 0; j < 4; j++) {
            const int t = min(tg + j, T - 1);
            tx[j] = tgt_x[t];
            ty[j] = tgt_y[t];
        }
    }

    float o0[4], o1[4];
#pragma unroll
    for (int j = 0; j < 4; j++) {
        const float fx = fmaf(tx[j], inv_dx, ox);
        const float fy = fmaf(ty[j], inv_dy, oy);
        const float ixf = floorf(fx);            // in [0, nx-2] by data bounds
        const float iyf = floorf(fy);            // in [0, ny-2]
        const float u = fx - ixf;
        const float v = fy - iyf;
        const float basef = fmaf(iyf, nxf, ixf); // exact: < 2^24
        const unsigned off = (unsigned)__float2int_rn(basef) << 6;

        const uint4 cv = __ldg(reinterpret_cast<const uint4*>(cellp + off));

        const float s  = u + v;
        const float m  = 1.0f - s;
        const float mn = fminf(m, 0.0f);
        const float wA  = fabsf(m);
        const float w10 = u + mn;          // lower: u      upper: 1-v
        const float w01 = v + mn;          // lower: v      upper: 1-u
        const unsigned ua = (m >= 0.0f) ? cv.x : cv.w;

        const float2 fA  = __half22float2(u2h(ua));
        const float2 f10 = __half22float2(u2h(cv.y));
        const float2 f01 = __half22float2(u2h(cv.z));

        o0[j] = fmaf(wA, fA.x, fmaf(w10, f10.x, w01 * f01.x));
        o1[j] = fmaf(wA, fA.y, fmaf(w10, f10.y, w01 * f01.y));
    }

    const int b0 = 2 * p;
    if (full) {
        *reinterpret_cast<float4*>(out + (size_t)b0 * T + tg) =
            make_float4(o0[0], o0[1], o0[2], o0[3]);
        *reinterpret_cast<float4*>(out + (size_t)(b0 + 1) * T + tg) =
            make_float4(o1[0], o1[1], o1[2], o1[3]);
    } else {
#pragma unroll
        for (int j = 0; j < 4; j++) {
            if (tg + j < T) {
                out[(size_t)b0 * T + tg + j] = o0[j];
                out[(size_t)(b0 + 1) * T + tg + j] = o1[j];
            }
        }
    }
}

// ---------------------------------------------------------------------------
// Generic fallback (any B), fp32 exact, full clamping.
// ---------------------------------------------------------------------------
__global__ void interp_generic_kernel(
    const float* __restrict__ x,
    const float* __restrict__ src_x,
    const float* __restrict__ src_y,
    const float* __restrict__ tgt_x,
    const float* __restrict__ tgt_y,
    const int* __restrict__ p_nx,
    const int* __restrict__ p_ny,
    float* __restrict__ out,
    int T, int B, int N)
{
    int t = blockIdx.x * blockDim.x + threadIdx.x;
    if (t >= T) return;

    const int nx = p_nx[0];
    const int ny = p_ny[0];
    const float x0 = src_x[0];
    const float x1 = src_x[nx - 1];
    const float y0 = src_y[0];
    const float y1 = src_y[(size_t)(ny - 1) * nx];
    const float inv_dx = (float)(nx - 1) / (x1 - x0);
    const float inv_dy = (float)(ny - 1) / (y1 - y0);

    const float fx = (tgt_x[t] - x0) * inv_dx;
    const float fy = (tgt_y[t] - y0) * inv_dy;

    float ixf = fminf(fmaxf(floorf(fx), 0.0f), (float)(nx - 2));
    float iyf = fminf(fmaxf(floorf(fy), 0.0f), (float)(ny - 2));
    const float u = fx - ixf;
    const float v = fy - iyf;
    const int base = (int)iyf * nx + (int)ixf;

    const bool lower = (u + v <= 1.0f);
    const int iA = lower ? base : (base + nx + 1);
    const int iB = base + 1;
    const int iC = base + nx;
    const float wA = lower ? (1.0f - u - v) : (u + v - 1.0f);
    const float wB = lower ? u : (1.0f - v);
    const float wC = lower ? v : (1.0f - u);

    for (int b = 0; b < B; b++) {
        const float* xb = x + (size_t)b * N;
        out[(size_t)b * T + t] = wA * xb[iA] + wB * xb[iB] + wC * xb[iC];
    }
}

extern "C" void kernel_launch(void* const* d_in, const int* in_sizes, int n_in,
                              void* d_out, int out_size)
{
    const float* x     = (const float*)d_in[0];
    const float* src_x = (const float*)d_in[1];
    const float* src_y = (const float*)d_in[2];
    const float* tgt_x = (const float*)d_in[3];
    const float* tgt_y = (const float*)d_in[4];
    const int*   p_nx  = (const int*)d_in[5];
    const int*   p_ny  = (const int*)d_in[6];
    float* out = (float*)d_out;

    const int N = in_sizes[1];          // nx*ny grid points
    const int T = in_sizes[3];          // target count
    const int B = in_sizes[0] / N;      // batches

    if (B == NB && N <= MAX_N) {
        // Host-side shape inference: square grid, N = nx*nx, nx % 4 == 0.
        int nxh = 1;
        while (nxh * nxh < N) nxh++;
        if (nxh * nxh == N && (nxh & 3) == 0 && nxh >= 8) {
            // Fast path: 2 kernel nodes total; consts computed inside prep.
            dim3 grid((nxh + 255) / 256, nxh - 1);   // x: 64 quads/block, y: rows
            prep_cell_v6<<<grid, 256>>>(x, src_x, src_y, nxh, nxh, N);
        } else {
            prep_consts<<<1, 1>>>(src_x, src_y, p_nx, p_ny);
            const int prep_threads = 4 * N;
            prep_cell_scalar<<<(prep_threads + 255) / 256, 256>>>(x, p_nx, p_ny, N);
        }

        const int blocks = (T + 255) / 256;
        interp_fp16_v5<<<blocks, 256>>>(tgt_x, tgt_y, out, T);
    } else {
        const int threads = 256;
        interp_generic_kernel<<<(T + threads - 1) / threads, threads>>>(
            x, src_x, src_y, tgt_x, tgt_y, p_nx, p_ny, out, T, B, N);
    }
}

// round 15
// speedup vs baseline: 1.0602x; 1.0010x over previous
#include <cuda_runtime.h>
#include <cuda_fp16.h>
#include <cstddef>

#define MAX_N (512 * 512)
#define NB 8

// Cell table: for each grid cell c = jj*nx+ii, 4 x uint4 (one per batch-pair p).
// Each uint4 = 4 half2: (v00,v10,v01,v11), each half2 = (batch 2p, batch 2p+1).
// 64B per cell.
__device__ uint4 g_cell[(size_t)MAX_N * 4];

// Uniform constants for interp:
// [0]=ox(=-x0*inv_dx) [1]=oy [2]=inv_dx [3]=inv_dy [4]=nxm2 [5]=nym2 [6]=nx(bits) [7]=nxf
__device__ __align__(16) float g_consts[8];

static __device__ __forceinline__ unsigned h2u(__half2 h) {
    return *reinterpret_cast<unsigned*>(&h);
}
static __device__ __forceinline__ __half2 u2h(unsigned u) {
    return *reinterpret_cast<__half2*>(&u);
}

// ---------------------------------------------------------------------------
// Prep v7: octet-amortized, 2D grid. blockIdx.y = row jj (0..ny-2);
// thread = (octet column, batch-pair p). Each thread builds 8 consecutive
// cells of one row for its pair: 12 loads + 18 converts + 8 stores for
// 8 cell-pairs (~6.25 instr/cp vs ~7.5 in v6). Each point converted once
// within the thread and shared between neighboring cells.
// Thread (0,0,0) computes the interp constants inline (no serial node).
// Requires nx % 8 == 0 (host-checked); scalar fallback otherwise.
// ---------------------------------------------------------------------------
__global__ void __launch_bounds__(256) prep_cell_v7(
    const float* __restrict__ x,
    const float* __restrict__ src_x,
    const float* __restrict__ src_y,
    int nx, int ny, int N)
{
    if (blockIdx.x == 0 && blockIdx.y == 0 && threadIdx.x == 0) {
        const float x0 = src_x[0];
        const float x1 = src_x[nx - 1];
        const float y0 = src_y[0];
        const float y1 = src_y[(size_t)(ny - 1) * nx];
        const float inv_dx = (float)(nx - 1) / (x1 - x0);
        const float inv_dy = (float)(ny - 1) / (y1 - y0);
        g_consts[0] = -x0 * inv_dx;
        g_consts[1] = -y0 * inv_dy;
        g_consts[2] = inv_dx;
        g_consts[3] = inv_dy;
        g_consts[4] = (float)(nx - 2);
        g_consts[5] = (float)(ny - 2);
        g_consts[6] = __int_as_float(nx);
        g_consts[7] = (float)nx;
    }

    const int jj   = blockIdx.y;
    const int ocol = blockIdx.x * 64 + (threadIdx.x >> 2);  // octet column
    const int p    = threadIdx.x & 3;
    const int ii0  = ocol * 8;
    if (ii0 >= nx) return;

    const int c0 = jj * nx + ii0;

    const float* __restrict__ xb0 = x + (size_t)(2 * p) * N;
    const float* __restrict__ xb1 = xb0 + N;

    // Load 9-wide segments of rows jj and jj+1 for both planes of this pair.
    float r0[9], r1[9], s0[9], s1[9];
    float4 v;
    v = *reinterpret_cast<const float4*>(xb0 + c0);
    r0[0] = v.x; r0[1] = v.y; r0[2] = v.z; r0[3] = v.w;
    v = *reinterpret_cast<const float4*>(xb0 + c0 + 4);
    r0[4] = v.x; r0[5] = v.y; r0[6] = v.z; r0[7] = v.w;
    r0[8] = __ldg(xb0 + min(c0 + 8, N - 1));

    v = *reinterpret_cast<const float4*>(xb0 + c0 + nx);
    r1[0] = v.x; r1[1] = v.y; r1[2] = v.z; r1[3] = v.w;
    v = *reinterpret_cast<const float4*>(xb0 + c0 + nx + 4);
    r1[4] = v.x; r1[5] = v.y; r1[6] = v.z; r1[7] = v.w;
    r1[8] = __ldg(xb0 + min(c0 + nx + 8, N - 1));

    v = *reinterpret_cast<const float4*>(xb1 + c0);
    s0[0] = v.x; s0[1] = v.y; s0[2] = v.z; s0[3] = v.w;
    v = *reinterpret_cast<const float4*>(xb1 + c0 + 4);
    s0[4] = v.x; s0[5] = v.y; s0[6] = v.z; s0[7] = v.w;
    s0[8] = __ldg(xb1 + min(c0 + 8, N - 1));

    v = *reinterpret_cast<const float4*>(xb1 + c0 + nx);
    s1[0] = v.x; s1[1] = v.y; s1[2] = v.z; s1[3] = v.w;
    v = *reinterpret_cast<const float4*>(xb1 + c0 + nx + 4);
    s1[4] = v.x; s1[5] = v.y; s1[6] = v.z; s1[7] = v.w;
    s1[8] = __ldg(xb1 + min(c0 + nx + 8, N - 1));

    // Convert each point exactly once.
    unsigned h0[9], h1[9];
#pragma unroll
    for (int i = 0; i < 9; i++) {
        h0[i] = h2u(__floats2half2_rn(r0[i], s0[i]));
        h1[i] = h2u(__floats2half2_rn(r1[i], s1[i]));
    }

    uint4* __restrict__ dst = &g_cell[(size_t)c0 * 4 + p];
    const int imax = min(8, nx - 1 - ii0);   // cells with ii <= nx-2
#pragma unroll
    for (int i = 0; i < 8; i++) {
        if (i < imax) {
            uint4 w;
            w.x = h0[i];
            w.y = h0[i + 1];
            w.z = h1[i];
            w.w = h1[i + 1];
            dst[(size_t)i * 4] = w;
        }
    }
}

// ---------------------------------------------------------------------------
// Fallback consts kernel + scalar prep (only when shape inference fails).
// ---------------------------------------------------------------------------
__global__ void prep_consts(
    const float* __restrict__ src_x,
    const float* __restrict__ src_y,
    const int* __restrict__ p_nx,
    const int* __restrict__ p_ny)
{
    const int nx = p_nx[0];
    const int ny = p_ny[0];
    const float x0 = src_x[0];
    const float x1 = src_x[nx - 1];
    const float y0 = src_y[0];
    const float y1 = src_y[(size_t)(ny - 1) * nx];
    const float inv_dx = (float)(nx - 1) / (x1 - x0);
    const float inv_dy = (float)(ny - 1) / (y1 - y0);
    g_consts[0] = -x0 * inv_dx;
    g_consts[1] = -y0 * inv_dy;
    g_consts[2] = inv_dx;
    g_consts[3] = inv_dy;
    g_consts[4] = (float)(nx - 2);
    g_consts[5] = (float)(ny - 2);
    g_consts[6] = __int_as_float(nx);
    g_consts[7] = (float)nx;
}

__global__ void __launch_bounds__(256) prep_cell_scalar(
    const float* __restrict__ x,
    const int* __restrict__ p_nx,
    const int* __restrict__ p_ny,
    int N)
{
    const int idx = blockIdx.x * blockDim.x + threadIdx.x;
    const int c = idx >> 2;
    const int p = idx & 3;
    if (c >= N) return;
    const int nx = p_nx[0];
    const int ny = p_ny[0];
    const int jj = c / nx;
    const int ii = c - jj * nx;
    if (ii > nx - 2 || jj > ny - 2) return;

    const float* __restrict__ xb0 = x + (size_t)(2 * p) * N;
    const float* __restrict__ xb1 = xb0 + N;
    uint4 w;
    w.x = h2u(__floats2half2_rn(__ldg(xb0 + c),          __ldg(xb1 + c)));
    w.y = h2u(__floats2half2_rn(__ldg(xb0 + c + 1),      __ldg(xb1 + c + 1)));
    w.z = h2u(__floats2half2_rn(__ldg(xb0 + c + nx),     __ldg(xb1 + c + nx)));
    w.w = h2u(__floats2half2_rn(__ldg(xb0 + c + nx + 1), __ldg(xb1 + c + nx + 1)));
    g_cell[(size_t)c * 4 + p] = w;
}

// ---------------------------------------------------------------------------
// Interp v5 (UNCHANGED — converged at ~25.9us, L1-wavefront plateau):
// no index clamps (targets in [eps,1-eps]); branch-free weights; one LDG.128
// per target per lane quad; regs capped via __launch_bounds__(256, 8).
// ---------------------------------------------------------------------------
__global__ void __launch_bounds__(256, 8) interp_fp16_v5(
    const float* __restrict__ tgt_x,
    const float* __restrict__ tgt_y,
    float* __restrict__ out,
    int T)
{
    const int lane = threadIdx.x & 31;
    const int warp = (blockIdx.x * blockDim.x + threadIdx.x) >> 5;
    const int g    = lane >> 2;
    const int p    = lane & 3;
    const int tg   = warp * 32 + g * 4;
    if (tg >= T) return;

    const float4 k0 = *reinterpret_cast<const float4*>(&g_consts[0]);
    const float4 k1 = *reinterpret_cast<const float4*>(&g_consts[4]);
    const float ox = k0.x, oy = k0.y, inv_dx = k0.z, inv_dy = k0.w;
    const float nxf = k1.w;

    const char* __restrict__ cellp = reinterpret_cast<const char*>(g_cell) + (p << 4);

    const bool full = (tg + 3 < T);

    float tx[4], ty[4];
    if (full) {
        const float4 tx4 = *reinterpret_cast<const float4*>(tgt_x + tg);
        const float4 ty4 = *reinterpret_cast<const float4*>(tgt_y + tg);
        tx[0] = tx4.x; tx[1] = tx4.y; tx[2] = tx4.z; tx[3] = tx4.w;
        ty[0] = ty4.x; ty[1] = ty4.y; ty[2] = ty4.z; ty[3] = ty4.w;
    } else {
#pragma unroll
        for (int j = 0; j < 4; j++) {
            const int t = min(tg + j, T - 1);
            tx[j] = tgt_x[t];
            ty[j] = tgt_y[t];
        }
    }

    float o0[4], o1[4];
#pragma unroll
    for (int j = 0; j < 4; j++) {
        const float fx = fmaf(tx[j], inv_dx, ox);
        const float fy = fmaf(ty[j], inv_dy, oy);
        const float ixf = floorf(fx);            // in [0, nx-2] by data bounds
        const float iyf = floorf(fy);            // in [0, ny-2]
        const float u = fx - ixf;
        const float v = fy - iyf;
        const float basef = fmaf(iyf, nxf, ixf); // exact: < 2^24
        const unsigned off = (unsigned)__float2int_rn(basef) << 6;

        const uint4 cv = __ldg(reinterpret_cast<const uint4*>(cellp + off));

        const float s  = u + v;
        const float m  = 1.0f - s;
        const float mn = fminf(m, 0.0f);
        const float wA  = fabsf(m);
        const float w10 = u + mn;          // lower: u      upper: 1-v
        const float w01 = v + mn;          // lower: v      upper: 1-u
        const unsigned ua = (m >= 0.0f) ? cv.x : cv.w;

        const float2 fA  = __half22float2(u2h(ua));
        const float2 f10 = __half22float2(u2h(cv.y));
        const float2 f01 = __half22float2(u2h(cv.z));

        o0[j] = fmaf(wA, fA.x, fmaf(w10, f10.x, w01 * f01.x));
        o1[j] = fmaf(wA, fA.y, fmaf(w10, f10.y, w01 * f01.y));
    }

    const int b0 = 2 * p;
    if (full) {
        *reinterpret_cast<float4*>(out + (size_t)b0 * T + tg) =
            make_float4(o0[0], o0[1], o0[2], o0[3]);
        *reinterpret_cast<float4*>(out + (size_t)(b0 + 1) * T + tg) =
            make_float4(o1[0], o1[1], o1[2], o1[3]);
    } else {
#pragma unroll
        for (int j = 0; j < 4; j++) {
            if (tg + j < T) {
                out[(size_t)b0 * T + tg + j] = o0[j];
                out[(size_t)(b0 + 1) * T + tg + j] = o1[j];
            }
        }
    }
}

// ---------------------------------------------------------------------------
// Generic fallback (any B), fp32 exact, full clamping.
// ---------------------------------------------------------------------------
__global__ void interp_generic_kernel(
    const float* __restrict__ x,
    const float* __restrict__ src_x,
    const float* __restrict__ src_y,
    const float* __restrict__ tgt_x,
    const float* __restrict__ tgt_y,
    const int* __restrict__ p_nx,
    const int* __restrict__ p_ny,
    float* __restrict__ out,
    int T, int B, int N)
{
    int t = blockIdx.x * blockDim.x + threadIdx.x;
    if (t >= T) return;

    const int nx = p_nx[0];
    const int ny = p_ny[0];
    const float x0 = src_x[0];
    const float x1 = src_x[nx - 1];
    const float y0 = src_y[0];
    const float y1 = src_y[(size_t)(ny - 1) * nx];
    const float inv_dx = (float)(nx - 1) / (x1 - x0);
    const float inv_dy = (float)(ny - 1) / (y1 - y0);

    const float fx = (tgt_x[t] - x0) * inv_dx;
    const float fy = (tgt_y[t] - y0) * inv_dy;

    float ixf = fminf(fmaxf(floorf(fx), 0.0f), (float)(nx - 2));
    float iyf = fminf(fmaxf(floorf(fy), 0.0f), (float)(ny - 2));
    const float u = fx - ixf;
    const float v = fy - iyf;
    const int base = (int)iyf * nx + (int)ixf;

    const bool lower = (u + v <= 1.0f);
    const int iA = lower ? base : (base + nx + 1);
    const int iB = base + 1;
    const int iC = base + nx;
    const float wA = lower ? (1.0f - u - v) : (u + v - 1.0f);
    const float wB = lower ? u : (1.0f - v);
    const float wC = lower ? v : (1.0f - u);

    for (int b = 0; b < B; b++) {
        const float* xb = x + (size_t)b * N;
        out[(size_t)b * T + t] = wA * xb[iA] + wB * xb[iB] + wC * xb[iC];
    }
}

extern "C" void kernel_launch(void* const* d_in, const int* in_sizes, int n_in,
                              void* d_out, int out_size)
{
    const float* x     = (const float*)d_in[0];
    const float* src_x = (const float*)d_in[1];
    const float* src_y = (const float*)d_in[2];
    const float* tgt_x = (const float*)d_in[3];
    const float* tgt_y = (const float*)d_in[4];
    const int*   p_nx  = (const int*)d_in[5];
    const int*   p_ny  = (const int*)d_in[6];
    float* out = (float*)d_out;

    const int N = in_sizes[1];          // nx*ny grid points
    const int T = in_sizes[3];          // target count
    const int B = in_sizes[0] / N;      // batches

    if (B == NB && N <= MAX_N) {
        // Host-side shape inference: square grid, N = nx*nx, nx % 8 == 0.
        int nxh = 1;
        while (nxh * nxh < N) nxh++;
        if (nxh * nxh == N && (nxh & 7) == 0 && nxh >= 16) {
            // Fast path: 2 kernel nodes; consts computed inside prep.
            // x: 64 octets per block (256 threads = 64 octets x 4 pairs).
            dim3 grid((nxh / 8 + 63) / 64, nxh - 1);
            prep_cell_v7<<<grid, 256>>>(x, src_x, src_y, nxh, nxh, N);
        } else {
            prep_consts<<<1, 1>>>(src_x, src_y, p_nx, p_ny);
            const int prep_threads = 4 * N;
            prep_cell_scalar<<<(prep_threads + 255) / 256, 256>>>(x, p_nx, p_ny, N);
        }

        const int blocks = (T + 255) / 256;
        interp_fp16_v5<<<blocks, 256>>>(tgt_x, tgt_y, out, T);
    } else {
        const int threads = 256;
        interp_generic_kernel<<<(T + threads - 1) / threads, threads>>>(
            x, src_x, src_y, tgt_x, tgt_y, p_nx, p_ny, out, T, B, N);
    }
}

// round 16
// speedup vs baseline: 1.0777x; 1.0165x over previous
#include <cuda_runtime.h>
#include <cuda_fp16.h>
#include <cstddef>

#define MAX_N (512 * 512)
#define NB 8

// Cell table: for each grid cell c = jj*nx+ii, 4 x uint4 (one per batch-pair p).
// Each uint4 = 4 half2: (v00,v10,v01,v11), each half2 = (batch 2p, batch 2p+1).
// 64B per cell.
__device__ uint4 g_cell[(size_t)MAX_N * 4];

// Uniform constants:
// [0]=ox(=-x0*inv_dx) [1]=oy [2]=inv_dx [3]=inv_dy [4]=nxm2 [5]=nym2 [6]=nx(bits) [7]=nxf
__device__ __align__(16) float g_consts[8];

static __device__ __forceinline__ unsigned h2u(__half2 h) {
    return *reinterpret_cast<unsigned*>(&h);
}
static __device__ __forceinline__ __half2 u2h(unsigned u) {
    return *reinterpret_cast<__half2*>(&u);
}

// ---------------------------------------------------------------------------
// Prep v8: 1D quad layout (best measured: 6.9us as v3), NX compile-time so
// the per-thread row split is shift/mask, not integer division. Square grid
// (ny == NX) guaranteed by host dispatch. Thread 0 writes interp consts.
// ---------------------------------------------------------------------------
template <int NX>
__global__ void __launch_bounds__(256) prep_cell_v8(
    const float* __restrict__ x,
    const float* __restrict__ src_x,
    const float* __restrict__ src_y,
    int N)
{
    const int idx = blockIdx.x * blockDim.x + threadIdx.x;

    if (idx == 0) {
        const float x0 = src_x[0];
        const float x1 = src_x[NX - 1];
        const float y0 = src_y[0];
        const float y1 = src_y[(size_t)(NX - 1) * NX];
        const float inv_dx = (float)(NX - 1) / (x1 - x0);
        const float inv_dy = (float)(NX - 1) / (y1 - y0);
        g_consts[0] = -x0 * inv_dx;
        g_consts[1] = -y0 * inv_dy;
        g_consts[2] = inv_dx;
        g_consts[3] = inv_dy;
        g_consts[4] = (float)(NX - 2);
        g_consts[5] = (float)(NX - 2);
        g_consts[6] = __int_as_float(NX);
        g_consts[7] = (float)NX;
    }

    const int q  = idx >> 2;         // cell quad
    const int p  = idx & 3;          // batch pair
    const int c0 = q * 4;
    if (c0 >= N) return;

    const int jj  = c0 / NX;         // compile-time NX -> shift
    const int ii0 = c0 - jj * NX;    // -> mask
    if (jj > NX - 2) return;         // last row has no cells

    const float* __restrict__ xb0 = x + (size_t)(2 * p) * N;
    const float* __restrict__ xb1 = xb0 + N;

    float r0[5], r1[5], s0[5], s1[5];
    float4 v;
    v = *reinterpret_cast<const float4*>(xb0 + c0);
    r0[0] = v.x; r0[1] = v.y; r0[2] = v.z; r0[3] = v.w;
    r0[4] = __ldg(xb0 + min(c0 + 4, N - 1));
    v = *reinterpret_cast<const float4*>(xb0 + c0 + NX);
    r1[0] = v.x; r1[1] = v.y; r1[2] = v.z; r1[3] = v.w;
    r1[4] = __ldg(xb0 + min(c0 + NX + 4, N - 1));
    v = *reinterpret_cast<const float4*>(xb1 + c0);
    s0[0] = v.x; s0[1] = v.y; s0[2] = v.z; s0[3] = v.w;
    s0[4] = __ldg(xb1 + min(c0 + 4, N - 1));
    v = *reinterpret_cast<const float4*>(xb1 + c0 + NX);
    s1[0] = v.x; s1[1] = v.y; s1[2] = v.z; s1[3] = v.w;
    s1[4] = __ldg(xb1 + min(c0 + NX + 4, N - 1));

    unsigned h0[5], h1[5];
#pragma unroll
    for (int i = 0; i < 5; i++) {
        h0[i] = h2u(__floats2half2_rn(r0[i], s0[i]));
        h1[i] = h2u(__floats2half2_rn(r1[i], s1[i]));
    }

    uint4* __restrict__ dst = &g_cell[(size_t)c0 * 4 + p];
    const int imax = min(4, NX - 1 - ii0);   // cells with ii <= NX-2
#pragma unroll
    for (int i = 0; i < 4; i++) {
        if (i < imax) {
            uint4 w;
            w.x = h0[i];
            w.y = h0[i + 1];
            w.z = h1[i];
            w.w = h1[i + 1];
            dst[(size_t)i * 4] = w;
        }
    }
}

// ---------------------------------------------------------------------------
// Interp v6: v5 with NX compile-time — drops the k1 consts load entirely
// (nxf is an FFMA immediate). Otherwise identical to the converged v5.
// ---------------------------------------------------------------------------
template <int NX>
__global__ void __launch_bounds__(256, 8) interp_fp16_v6(
    const float* __restrict__ tgt_x,
    const float* __restrict__ tgt_y,
    float* __restrict__ out,
    int T)
{
    const int lane = threadIdx.x & 31;
    const int warp = (blockIdx.x * blockDim.x + threadIdx.x) >> 5;
    const int g    = lane >> 2;
    const int p    = lane & 3;
    const int tg   = warp * 32 + g * 4;
    if (tg >= T) return;

    const float4 k0 = *reinterpret_cast<const float4*>(&g_consts[0]);
    const float ox = k0.x, oy = k0.y, inv_dx = k0.z, inv_dy = k0.w;

    const char* __restrict__ cellp = reinterpret_cast<const char*>(g_cell) + (p << 4);

    const bool full = (tg + 3 < T);

    float tx[4], ty[4];
    if (full) {
        const float4 tx4 = *reinterpret_cast<const float4*>(tgt_x + tg);
        const float4 ty4 = *reinterpret_cast<const float4*>(tgt_y + tg);
        tx[0] = tx4.x; tx[1] = tx4.y; tx[2] = tx4.z; tx[3] = tx4.w;
        ty[0] = ty4.x; ty[1] = ty4.y; ty[2] = ty4.z; ty[3] = ty4.w;
    } else {
#pragma unroll
        for (int j = 0; j < 4; j++) {
            const int t = min(tg + j, T - 1);
            tx[j] = tgt_x[t];
            ty[j] = tgt_y[t];
        }
    }

    float o0[4], o1[4];
#pragma unroll
    for (int j = 0; j < 4; j++) {
        const float fx = fmaf(tx[j], inv_dx, ox);
        const float fy = fmaf(ty[j], inv_dy, oy);
        const float ixf = floorf(fx);                 // in [0, NX-2] by data bounds
        const float iyf = floorf(fy);
        const float u = fx - ixf;
        const float v = fy - iyf;
        const float basef = fmaf(iyf, (float)NX, ixf);  // FFMA-imm; exact < 2^24
        const unsigned off = (unsigned)__float2int_rn(basef) << 6;

        const uint4 cv = __ldg(reinterpret_cast<const uint4*>(cellp + off));

        const float s  = u + v;
        const float m  = 1.0f - s;
        const float mn = fminf(m, 0.0f);
        const float wA  = fabsf(m);
        const float w10 = u + mn;          // lower: u      upper: 1-v
        const float w01 = v + mn;          // lower: v      upper: 1-u
        const unsigned ua = (m >= 0.0f) ? cv.x : cv.w;

        const float2 fA  = __half22float2(u2h(ua));
        const float2 f10 = __half22float2(u2h(cv.y));
        const float2 f01 = __half22float2(u2h(cv.z));

        o0[j] = fmaf(wA, fA.x, fmaf(w10, f10.x, w01 * f01.x));
        o1[j] = fmaf(wA, fA.y, fmaf(w10, f10.y, w01 * f01.y));
    }

    const int b0 = 2 * p;
    if (full) {
        *reinterpret_cast<float4*>(out + (size_t)b0 * T + tg) =
            make_float4(o0[0], o0[1], o0[2], o0[3]);
        *reinterpret_cast<float4*>(out + (size_t)(b0 + 1) * T + tg) =
            make_float4(o1[0], o1[1], o1[2], o1[3]);
    } else {
#pragma unroll
        for (int j = 0; j < 4; j++) {
            if (tg + j < T) {
                out[(size_t)b0 * T + tg + j] = o0[j];
                out[(size_t)(b0 + 1) * T + tg + j] = o1[j];
            }
        }
    }
}

// ---------------------------------------------------------------------------
// Square-grid fallback (nx != 512): consts kernel + scalar prep + runtime-nx
// interp (v5 semantics, reads nxf from g_consts).
// ---------------------------------------------------------------------------
__global__ void prep_consts(
    const float* __restrict__ src_x,
    const float* __restrict__ src_y,
    const int* __restrict__ p_nx,
    const int* __restrict__ p_ny)
{
    const int nx = p_nx[0];
    const int ny = p_ny[0];
    const float x0 = src_x[0];
    const float x1 = src_x[nx - 1];
    const float y0 = src_y[0];
    const float y1 = src_y[(size_t)(ny - 1) * nx];
    const float inv_dx = (float)(nx - 1) / (x1 - x0);
    const float inv_dy = (float)(ny - 1) / (y1 - y0);
    g_consts[0] = -x0 * inv_dx;
    g_consts[1] = -y0 * inv_dy;
    g_consts[2] = inv_dx;
    g_consts[3] = inv_dy;
    g_consts[4] = (float)(nx - 2);
    g_consts[5] = (float)(ny - 2);
    g_consts[6] = __int_as_float(nx);
    g_consts[7] = (float)nx;
}

__global__ void __launch_bounds__(256) prep_cell_scalar(
    const float* __restrict__ x,
    const int* __restrict__ p_nx,
    const int* __restrict__ p_ny,
    int N)
{
    const int idx = blockIdx.x * blockDim.x + threadIdx.x;
    const int c = idx >> 2;
    const int p = idx & 3;
    if (c >= N) return;
    const int nx = p_nx[0];
    const int ny = p_ny[0];
    const int jj = c / nx;
    const int ii = c - jj * nx;
    if (ii > nx - 2 || jj > ny - 2) return;

    const float* __restrict__ xb0 = x + (size_t)(2 * p) * N;
    const float* __restrict__ xb1 = xb0 + N;
    uint4 w;
    w.x = h2u(__floats2half2_rn(__ldg(xb0 + c),          __ldg(xb1 + c)));
    w.y = h2u(__floats2half2_rn(__ldg(xb0 + c + 1),      __ldg(xb1 + c + 1)));
    w.z = h2u(__floats2half2_rn(__ldg(xb0 + c + nx),     __ldg(xb1 + c + nx)));
    w.w = h2u(__floats2half2_rn(__ldg(xb0 + c + nx + 1), __ldg(xb1 + c + nx + 1)));
    g_cell[(size_t)c * 4 + p] = w;
}

__global__ void __launch_bounds__(256, 8) interp_fp16_rt(
    const float* __restrict__ tgt_x,
    const float* __restrict__ tgt_y,
    float* __restrict__ out,
    int T)
{
    const int lane = threadIdx.x & 31;
    const int warp = (blockIdx.x * blockDim.x + threadIdx.x) >> 5;
    const int g    = lane >> 2;
    const int p    = lane & 3;
    const int tg   = warp * 32 + g * 4;
    if (tg >= T) return;

    const float4 k0 = *reinterpret_cast<const float4*>(&g_consts[0]);
    const float4 k1 = *reinterpret_cast<const float4*>(&g_consts[4]);
    const float ox = k0.x, oy = k0.y, inv_dx = k0.z, inv_dy = k0.w;
    const float nxf = k1.w;

    const char* __restrict__ cellp = reinterpret_cast<const char*>(g_cell) + (p << 4);
    const bool full = (tg + 3 < T);

    float tx[4], ty[4];
    if (full) {
        const float4 tx4 = *reinterpret_cast<const float4*>(tgt_x + tg);
        const float4 ty4 = *reinterpret_cast<const float4*>(tgt_y + tg);
        tx[0] = tx4.x; tx[1] = tx4.y; tx[2] = tx4.z; tx[3] = tx4.w;
        ty[0] = ty4.x; ty[1] = ty4.y; ty[2] = ty4.z; ty[3] = ty4.w;
    } else {
#pragma unroll
        for (int j = 0; j < 4; j++) {
            const int t = min(tg + j, T - 1);
            tx[j] = tgt_x[t];
            ty[j] = tgt_y[t];
        }
    }

    float o0[4], o1[4];
#pragma unroll
    for (int j = 0; j < 4; j++) {
        const float fx = fmaf(tx[j], inv_dx, ox);
        const float fy = fmaf(ty[j], inv_dy, oy);
        const float ixf = floorf(fx);
        const float iyf = floorf(fy);
        const float u = fx - ixf;
        const float v = fy - iyf;
        const float basef = fmaf(iyf, nxf, ixf);
        const unsigned off = (unsigned)__float2int_rn(basef) << 6;

        const uint4 cv = __ldg(reinterpret_cast<const uint4*>(cellp + off));

        const float s  = u + v;
        const float m  = 1.0f - s;
        const float mn = fminf(m, 0.0f);
        const float wA  = fabsf(m);
        const float w10 = u + mn;
        const float w01 = v + mn;
        const unsigned ua = (m >= 0.0f) ? cv.x : cv.w;

        const float2 fA  = __half22float2(u2h(ua));
        const float2 f10 = __half22float2(u2h(cv.y));
        const float2 f01 = __half22float2(u2h(cv.z));

        o0[j] = fmaf(wA, fA.x, fmaf(w10, f10.x, w01 * f01.x));
        o1[j] = fmaf(wA, fA.y, fmaf(w10, f10.y, w01 * f01.y));
    }

    const int b0 = 2 * p;
    if (full) {
        *reinterpret_cast<float4*>(out + (size_t)b0 * T + tg) =
            make_float4(o0[0], o0[1], o0[2], o0[3]);
        *reinterpret_cast<float4*>(out + (size_t)(b0 + 1) * T + tg) =
            make_float4(o1[0], o1[1], o1[2], o1[3]);
    } else {
#pragma unroll
        for (int j = 0; j < 4; j++) {
            if (tg + j < T) {
                out[(size_t)b0 * T + tg + j] = o0[j];
                out[(size_t)(b0 + 1) * T + tg + j] = o1[j];
            }
        }
    }
}

// ---------------------------------------------------------------------------
// Generic fallback (any B), fp32 exact, full clamping.
// ---------------------------------------------------------------------------
__global__ void interp_generic_kernel(
    const float* __restrict__ x,
    const float* __restrict__ src_x,
    const float* __restrict__ src_y,
    const float* __restrict__ tgt_x,
    const float* __restrict__ tgt_y,
    const int* __restrict__ p_nx,
    const int* __restrict__ p_ny,
    float* __restrict__ out,
    int T, int B, int N)
{
    int t = blockIdx.x * blockDim.x + threadIdx.x;
    if (t >= T) return;

    const int nx = p_nx[0];
    const int ny = p_ny[0];
    const float x0 = src_x[0];
    const float x1 = src_x[nx - 1];
    const float y0 = src_y[0];
    const float y1 = src_y[(size_t)(ny - 1) * nx];
    const float inv_dx = (float)(nx - 1) / (x1 - x0);
    const float inv_dy = (float)(ny - 1) / (y1 - y0);

    const float fx = (tgt_x[t] - x0) * inv_dx;
    const float fy = (tgt_y[t] - y0) * inv_dy;

    float ixf = fminf(fmaxf(floorf(fx), 0.0f), (float)(nx - 2));
    float iyf = fminf(fmaxf(floorf(fy), 0.0f), (float)(ny - 2));
    const float u = fx - ixf;
    const float v = fy - iyf;
    const int base = (int)iyf * nx + (int)ixf;

    const bool lower = (u + v <= 1.0f);
    const int iA = lower ? base : (base + nx + 1);
    const int iB = base + 1;
    const int iC = base + nx;
    const float wA = lower ? (1.0f - u - v) : (u + v - 1.0f);
    const float wB = lower ? u : (1.0f - v);
    const float wC = lower ? v : (1.0f - u);

    for (int b = 0; b < B; b++) {
        const float* xb = x + (size_t)b * N;
        out[(size_t)b * T + t] = wA * xb[iA] + wB * xb[iB] + wC * xb[iC];
    }
}

extern "C" void kernel_launch(void* const* d_in, const int* in_sizes, int n_in,
                              void* d_out, int out_size)
{
    const float* x     = (const float*)d_in[0];
    const float* src_x = (const float*)d_in[1];
    const float* src_y = (const float*)d_in[2];
    const float* tgt_x = (const float*)d_in[3];
    const float* tgt_y = (const float*)d_in[4];
    const int*   p_nx  = (const int*)d_in[5];
    const int*   p_ny  = (const int*)d_in[6];
    float* out = (float*)d_out;

    const int N = in_sizes[1];          // nx*ny grid points
    const int T = in_sizes[3];          // target count
    const int B = in_sizes[0] / N;      // batches

    if (B == NB && N <= MAX_N) {
        // Host-side shape inference: square grid.
        int nxh = 1;
        while (nxh * nxh < N) nxh++;
        const bool square = (nxh * nxh == N);
        const int blocks = (T + 255) / 256;

        if (square && nxh == 512) {
            // Fast path: NX=512 compile-time specialization, 2 kernel nodes.
            const int prep_threads = N;   // one thread per (quad, pair)
            prep_cell_v8<512><<<(prep_threads + 255) / 256, 256>>>(
                x, src_x, src_y, N);
            interp_fp16_v6<512><<<blocks, 256>>>(tgt_x, tgt_y, out, T);
        } else {
            prep_consts<<<1, 1>>>(src_x, src_y, p_nx, p_ny);
            const int prep_threads = 4 * N;
            prep_cell_scalar<<<(prep_threads + 255) / 256, 256>>>(x, p_nx, p_ny, N);
            interp_fp16_rt<<<blocks, 256>>>(tgt_x, tgt_y, out, T);
        }
    } else {
        const int threads = 256;
        interp_generic_kernel<<<(T + threads - 1) / threads, threads>>>(
            x, src_x, src_y, tgt_x, tgt_y, p_nx, p_ny, out, T, B, N);
    }
}